// round 1
// baseline (speedup 1.0000x reference)
#include <cuda_runtime.h>
#include <math.h>

#define N_USERS 100000
#define N_ITEMS 50000
#define N_NODES 150000
#define EMB 64
#define NINT 128
#define MAX_EDGES 4000000

// ---------------- static device scratch (no allocations allowed) ----------------
__device__ int   g_deg[N_NODES];
__device__ float g_dis[N_NODES];
__device__ int   g_rowptr[N_NODES + 1];
__device__ int   g_cursor[N_NODES];
__device__ int2  g_edges[MAX_EDGES];                 // (t_idx, g_val as bits)
__device__ float g_embA[(size_t)N_NODES * EMB];
__device__ float g_embB[(size_t)N_NODES * EMB];
__device__ float g_P[(size_t)(N_NODES + 128) * NINT]; // padded for OOB-tile reads

// ---------------- precompute kernels ----------------
__global__ void zero_deg_kernel() {
    int i = blockIdx.x * blockDim.x + threadIdx.x;
    if (i < N_NODES) g_deg[i] = 0;
}

__global__ void hist_kernel(const int* __restrict__ h, int n) {
    int stride = gridDim.x * blockDim.x;
    for (int i = blockIdx.x * blockDim.x + threadIdx.x; i < n; i += stride)
        atomicAdd(&g_deg[h[i]], 1);
}

__global__ void dis_kernel() {
    int i = blockIdx.x * blockDim.x + threadIdx.x;
    if (i < N_NODES) {
        int d = g_deg[i];
        g_dis[i] = (d > 0) ? rsqrtf((float)d) : 0.0f;
    }
}

// single-block exclusive scan of g_deg -> g_rowptr, g_cursor
__global__ void scan_kernel() {
    __shared__ int wsum[32];
    const int tid = threadIdx.x;           // 1024 threads
    const int lane = tid & 31, wid = tid >> 5;
    int carry = 0;
    for (int base = 0; base < N_NODES; base += 1024) {
        int i = base + tid;
        int v = (i < N_NODES) ? g_deg[i] : 0;
        int x = v;
        #pragma unroll
        for (int d = 1; d < 32; d <<= 1) {
            int y = __shfl_up_sync(0xffffffffu, x, d);
            if (lane >= d) x += y;
        }
        if (lane == 31) wsum[wid] = x;
        __syncthreads();
        if (wid == 0) {
            int s = wsum[lane];
            #pragma unroll
            for (int d = 1; d < 32; d <<= 1) {
                int y = __shfl_up_sync(0xffffffffu, s, d);
                if (lane >= d) s += y;
            }
            wsum[lane] = s;
        }
        __syncthreads();
        int woff = (wid > 0) ? wsum[wid - 1] : 0;
        int excl = carry + woff + x - v;
        if (i < N_NODES) { g_rowptr[i] = excl; g_cursor[i] = excl; }
        carry += wsum[31];
        __syncthreads();
    }
    if (tid == 0) g_rowptr[N_NODES] = carry;
}

__global__ void scatter_kernel(const int* __restrict__ h, const int* __restrict__ t, int n) {
    int stride = gridDim.x * blockDim.x;
    for (int i = blockIdx.x * blockDim.x + threadIdx.x; i < n; i += stride) {
        int hh = h[i], tt = t[i];
        int pos = atomicAdd(&g_cursor[hh], 1);
        float v = g_dis[hh] * g_dis[tt];
        g_edges[pos] = make_int2(tt, __float_as_int(v));
    }
}

// embA = concat(user,item); out = embA/3
__global__ void init_kernel(const float* __restrict__ u, const float* __restrict__ it,
                            float* __restrict__ embA, float* __restrict__ out) {
    int i = blockIdx.x * blockDim.x + threadIdx.x;   // over float4s
    const int total4 = N_NODES * EMB / 4;
    if (i >= total4) return;
    const int ub4 = N_USERS * EMB / 4;
    float4 v = (i < ub4) ? ((const float4*)u)[i] : ((const float4*)it)[i - ub4];
    ((float4*)embA)[i] = v;
    const float third = 1.0f / 3.0f;
    float4 o = make_float4(v.x * third, v.y * third, v.z * third, v.w * third);
    ((float4*)out)[i] = o;
}

// ---------------- SPMM: warp per node ----------------
__global__ __launch_bounds__(256) void spmm_kernel(const float* __restrict__ xin,
                                                   float* __restrict__ xout) {
    const int lane = threadIdx.x & 31;
    const int n = (blockIdx.x << 3) + (threadIdx.x >> 5);
    if (n >= N_NODES) return;
    const int beg = g_rowptr[n], end = g_rowptr[n + 1];
    float ax = 0.f, ay = 0.f;
    int j = beg;
    for (; j + 4 <= end; j += 4) {
        int2 e0 = g_edges[j + 0];
        int2 e1 = g_edges[j + 1];
        int2 e2 = g_edges[j + 2];
        int2 e3 = g_edges[j + 3];
        float2 v0 = *((const float2*)(xin + (size_t)e0.x * EMB) + lane);
        float2 v1 = *((const float2*)(xin + (size_t)e1.x * EMB) + lane);
        float2 v2 = *((const float2*)(xin + (size_t)e2.x * EMB) + lane);
        float2 v3 = *((const float2*)(xin + (size_t)e3.x * EMB) + lane);
        float w0 = __int_as_float(e0.y), w1 = __int_as_float(e1.y);
        float w2 = __int_as_float(e2.y), w3 = __int_as_float(e3.y);
        ax = fmaf(w0, v0.x, ax); ay = fmaf(w0, v0.y, ay);
        ax = fmaf(w1, v1.x, ax); ay = fmaf(w1, v1.y, ay);
        ax = fmaf(w2, v2.x, ax); ay = fmaf(w2, v2.y, ay);
        ax = fmaf(w3, v3.x, ax); ay = fmaf(w3, v3.y, ay);
    }
    for (; j < end; j++) {
        int2 e = g_edges[j];
        float2 v = *((const float2*)(xin + (size_t)e.x * EMB) + lane);
        float w = __int_as_float(e.y);
        ax = fmaf(w, v.x, ax); ay = fmaf(w, v.y, ay);
    }
    ((float2*)(xout + (size_t)n * EMB))[lane] = make_float2(ax, ay);
}

// ---------------- intent1: P = softmax(X @ W), 128-node tile ----------------
#define SMEM1_BYTES ((64 * 129 + 64 * 128) * 4)
__global__ __launch_bounds__(256, 2) void intent1_kernel(const float* __restrict__ xin,
                                                         const float* __restrict__ W,
                                                         float* __restrict__ P) {
    extern __shared__ float smem[];
    float* sXT = smem;            // [64][129]  (k-major, padded)
    float* sW  = smem + 64 * 129; // [64][128]
    const int tid = threadIdx.x;
    const int node0 = blockIdx.x * 128;

    for (int i = tid; i < 64 * 128; i += 256) sW[i] = W[i];
    for (int i = tid; i < 128 * 16; i += 256) {
        int m = i >> 4;
        int k4 = (i & 15) << 2;
        int nd = node0 + m;
        float4 v = (nd < N_NODES) ? *(const float4*)(xin + (size_t)nd * EMB + k4)
                                  : make_float4(0.f, 0.f, 0.f, 0.f);
        sXT[(k4 + 0) * 129 + m] = v.x;
        sXT[(k4 + 1) * 129 + m] = v.y;
        sXT[(k4 + 2) * 129 + m] = v.z;
        sXT[(k4 + 3) * 129 + m] = v.w;
    }
    __syncthreads();

    const int tj = tid & 15, tm = tid >> 4;
    const int m0 = tm * 8, j0 = tj * 8;
    float acc[8][8];
    #pragma unroll
    for (int r = 0; r < 8; r++)
        #pragma unroll
        for (int c = 0; c < 8; c++) acc[r][c] = 0.f;

    for (int k = 0; k < 64; k++) {
        float a[8];
        #pragma unroll
        for (int r = 0; r < 8; r++) a[r] = sXT[k * 129 + m0 + r];
        float4 b0 = *(const float4*)(sW + k * 128 + j0);
        float4 b1 = *(const float4*)(sW + k * 128 + j0 + 4);
        float b[8] = {b0.x, b0.y, b0.z, b0.w, b1.x, b1.y, b1.z, b1.w};
        #pragma unroll
        for (int r = 0; r < 8; r++)
            #pragma unroll
            for (int c = 0; c < 8; c++)
                acc[r][c] = fmaf(a[r], b[c], acc[r][c]);
    }

    // row softmax: 16 lanes (tj) share each row, all within one warp
    #pragma unroll
    for (int r = 0; r < 8; r++) {
        float mx = acc[r][0];
        #pragma unroll
        for (int c = 1; c < 8; c++) mx = fmaxf(mx, acc[r][c]);
        #pragma unroll
        for (int o = 8; o > 0; o >>= 1) mx = fmaxf(mx, __shfl_xor_sync(0xffffffffu, mx, o));
        float e[8]; float s = 0.f;
        #pragma unroll
        for (int c = 0; c < 8; c++) { e[c] = __expf(acc[r][c] - mx); s += e[c]; }
        #pragma unroll
        for (int o = 8; o > 0; o >>= 1) s += __shfl_xor_sync(0xffffffffu, s, o);
        float inv = 1.0f / s;
        int nd = node0 + m0 + r;
        if (nd < N_NODES) {
            float4 o0 = make_float4(e[0] * inv, e[1] * inv, e[2] * inv, e[3] * inv);
            float4 o1 = make_float4(e[4] * inv, e[5] * inv, e[6] * inv, e[7] * inv);
            *(float4*)(P + (size_t)nd * NINT + j0)     = o0;
            *(float4*)(P + (size_t)nd * NINT + j0 + 4) = o1;
        }
    }
}

// ---------------- intent2: Y = P @ W^T; xio += Y; out += xio_new/3 ----------------
#define SMEM2_BYTES ((128 * 129 + 128 * 68) * 4)
__global__ __launch_bounds__(256, 2) void intent2_kernel(const float* __restrict__ P,
                                                         const float* __restrict__ W,
                                                         float* __restrict__ xio,
                                                         float* __restrict__ out) {
    extern __shared__ float smem[];
    float* sPT = smem;              // [128][129]  (j-major, padded)
    float* sWT = smem + 128 * 129;  // [128][68]   (j-major, padded)
    const int tid = threadIdx.x;
    const int node0 = blockIdx.x * 128;

    for (int i = tid; i < 64 * 128; i += 256) {
        int k = i >> 7, j = i & 127;
        sWT[j * 68 + k] = W[i];
    }
    for (int i = tid; i < 128 * 32; i += 256) {
        int m = i >> 5;
        int j4 = (i & 31) << 2;
        float4 v = *(const float4*)(P + (size_t)(node0 + m) * NINT + j4);
        sPT[(j4 + 0) * 129 + m] = v.x;
        sPT[(j4 + 1) * 129 + m] = v.y;
        sPT[(j4 + 2) * 129 + m] = v.z;
        sPT[(j4 + 3) * 129 + m] = v.w;
    }
    __syncthreads();

    const int tn = tid & 15, tm = tid >> 4;
    const int m0 = tm * 8, n0 = tn * 4;
    float acc[8][4];
    #pragma unroll
    for (int r = 0; r < 8; r++)
        #pragma unroll
        for (int c = 0; c < 4; c++) acc[r][c] = 0.f;

    for (int j = 0; j < 128; j++) {
        float4 b = *(const float4*)(sWT + j * 68 + n0);
        #pragma unroll
        for (int r = 0; r < 8; r++) {
            float a = sPT[j * 129 + m0 + r];
            acc[r][0] = fmaf(a, b.x, acc[r][0]);
            acc[r][1] = fmaf(a, b.y, acc[r][1]);
            acc[r][2] = fmaf(a, b.z, acc[r][2]);
            acc[r][3] = fmaf(a, b.w, acc[r][3]);
        }
    }

    const float third = 1.0f / 3.0f;
    #pragma unroll
    for (int r = 0; r < 8; r++) {
        int nd = node0 + m0 + r;
        if (nd < N_NODES) {
            size_t idx = (size_t)nd * EMB + n0;
            float4 g = *(const float4*)(xio + idx);
            float4 y = make_float4(acc[r][0] + g.x, acc[r][1] + g.y,
                                   acc[r][2] + g.z, acc[r][3] + g.w);
            *(float4*)(xio + idx) = y;
            float4 o = *(const float4*)(out + idx);
            o.x += y.x * third; o.y += y.y * third;
            o.z += y.z * third; o.w += y.w * third;
            *(float4*)(out + idx) = o;
        }
    }
}

// ---------------- launch ----------------
extern "C" void kernel_launch(void* const* d_in, const int* in_sizes, int n_in,
                              void* d_out, int out_size) {
    const float* user = (const float*)d_in[0];
    const float* item = (const float*)d_in[1];
    const float* W    = (const float*)d_in[2];
    const int*   hix  = (const int*)d_in[3];
    const int*   tix  = (const int*)d_in[4];
    const int n_edges = in_sizes[3];
    float* out = (float*)d_out;

    cudaFuncSetAttribute(intent1_kernel, cudaFuncAttributeMaxDynamicSharedMemorySize, SMEM1_BYTES);
    cudaFuncSetAttribute(intent2_kernel, cudaFuncAttributeMaxDynamicSharedMemorySize, SMEM2_BYTES);

    float *A, *B, *P;
    cudaGetSymbolAddress((void**)&A, g_embA);
    cudaGetSymbolAddress((void**)&B, g_embB);
    cudaGetSymbolAddress((void**)&P, g_P);

    const int TB = 256;
    // precompute
    zero_deg_kernel<<<(N_NODES + TB - 1) / TB, TB>>>();
    hist_kernel<<<4096, TB>>>(hix, n_edges);
    dis_kernel<<<(N_NODES + TB - 1) / TB, TB>>>();
    scan_kernel<<<1, 1024>>>();
    scatter_kernel<<<4096, TB>>>(hix, tix, n_edges);
    init_kernel<<<(N_NODES * EMB / 4 + TB - 1) / TB, TB>>>(user, item, A, out);

    const int spmm_blocks = (N_NODES + 7) / 8;
    const int tile_blocks = (N_NODES + 127) / 128;

    // layer 0: cur = A, gnn -> B, final layer emb in B
    spmm_kernel<<<spmm_blocks, TB>>>(A, B);
    intent1_kernel<<<tile_blocks, TB, SMEM1_BYTES>>>(A, W, P);
    intent2_kernel<<<tile_blocks, TB, SMEM2_BYTES>>>(P, W, B, out);

    // layer 1: cur = B, gnn -> A, final layer emb in A
    spmm_kernel<<<spmm_blocks, TB>>>(B, A);
    intent1_kernel<<<tile_blocks, TB, SMEM1_BYTES>>>(B, W, P);
    intent2_kernel<<<tile_blocks, TB, SMEM2_BYTES>>>(P, W, A, out);
}

// round 2
// speedup vs baseline: 1.4367x; 1.4367x over previous
#include <cuda_runtime.h>
#include <math.h>

#define N_USERS 100000
#define N_ITEMS 50000
#define N_NODES 150000
#define EMB 64
#define NINT 128
#define MAX_EDGES 4000000

#define N4 ((N_NODES + 3) / 4)          // 37500 int4 chunks of deg
#define NBLK ((N4 + 1023) / 1024)       // 37 scan blocks

// ---------------- static device scratch ----------------
__device__ int   g_deg[N_NODES];
__device__ float g_dis[N_NODES];
__device__ int   g_rowptr[N_NODES + 1];
__device__ int   g_cursor[N_NODES];
__device__ int   g_ecol[MAX_EDGES];
__device__ int   g_bsum[NBLK];
__device__ int   g_boff[NBLK];
__device__ float g_embA[(size_t)N_NODES * EMB];
__device__ float g_embB[(size_t)N_NODES * EMB];
__device__ float g_embS[(size_t)N_NODES * EMB];   // dis-scaled spmm input

// ---------------- packed fp32x2 helpers ----------------
__device__ __forceinline__ unsigned long long fma2(unsigned long long a,
                                                   unsigned long long b,
                                                   unsigned long long c) {
    unsigned long long d;
    asm("fma.rn.f32x2 %0, %1, %2, %3;" : "=l"(d) : "l"(a), "l"(b), "l"(c));
    return d;
}
__device__ __forceinline__ unsigned long long pk2(float x, float y) {
    unsigned long long r;
    asm("mov.b64 %0, {%1, %2};" : "=l"(r) : "f"(x), "f"(y));
    return r;
}
__device__ __forceinline__ float2 upk(unsigned long long v) {
    float2 f;
    asm("mov.b64 {%0, %1}, %2;" : "=f"(f.x), "=f"(f.y) : "l"(v));
    return f;
}

// ---------------- precompute ----------------
__global__ void zero_deg_kernel() {
    int i = blockIdx.x * blockDim.x + threadIdx.x;
    if (i < N_NODES) g_deg[i] = 0;
}

__global__ void hist_kernel(const int* __restrict__ h, int n) {
    int stride = gridDim.x * blockDim.x;
    for (int i = blockIdx.x * blockDim.x + threadIdx.x; i < n; i += stride)
        atomicAdd(&g_deg[h[i]], 1);
}

// phase 1: per-block sums of deg (4096 ints / block)
__global__ __launch_bounds__(1024) void scan_bsum_kernel() {
    __shared__ int ws[32];
    int t = threadIdx.x, b = blockIdx.x;
    int idx = b * 1024 + t;
    int4 v = (idx < N4) ? ((const int4*)g_deg)[idx] : make_int4(0, 0, 0, 0);
    int s = v.x + v.y + v.z + v.w;
    #pragma unroll
    for (int o = 16; o; o >>= 1) s += __shfl_xor_sync(0xffffffffu, s, o);
    if ((t & 31) == 0) ws[t >> 5] = s;
    __syncthreads();
    if (t < 32) {
        int x = ws[t];
        #pragma unroll
        for (int o = 16; o; o >>= 1) x += __shfl_xor_sync(0xffffffffu, x, o);
        if (t == 0) g_bsum[b] = x;
    }
}

// phase 2: exclusive scan of NBLK(=37) block sums
__global__ void scan_boff_kernel(int n_edges) {
    __shared__ int tmp[2];
    int t = threadIdx.x;   // 64 threads
    int v = (t < NBLK) ? g_bsum[t] : 0;
    int lane = t & 31, w = t >> 5;
    int x = v;
    #pragma unroll
    for (int o = 1; o < 32; o <<= 1) {
        int y = __shfl_up_sync(0xffffffffu, x, o);
        if (lane >= o) x += y;
    }
    if (lane == 31) tmp[w] = x;
    __syncthreads();
    int add = (w == 1) ? tmp[0] : 0;
    if (t < NBLK) g_boff[t] = x - v + add;
    if (t == 0) g_rowptr[N_NODES] = n_edges;
}

// phase 3: full exclusive scan write (rowptr, cursor) + dis
__global__ __launch_bounds__(1024) void scan_write_kernel() {
    __shared__ int ws[32];
    int t = threadIdx.x, b = blockIdx.x;
    int lane = t & 31, wid = t >> 5;
    int idx = b * 1024 + t;
    int4 v = (idx < N4) ? ((const int4*)g_deg)[idx] : make_int4(0, 0, 0, 0);
    int s = v.x + v.y + v.z + v.w;
    int x = s;
    #pragma unroll
    for (int o = 1; o < 32; o <<= 1) {
        int y = __shfl_up_sync(0xffffffffu, x, o);
        if (lane >= o) x += y;
    }
    if (lane == 31) ws[wid] = x;
    __syncthreads();
    if (wid == 0) {
        int z = ws[lane];
        #pragma unroll
        for (int o = 1; o < 32; o <<= 1) {
            int y = __shfl_up_sync(0xffffffffu, z, o);
            if (lane >= o) z += y;
        }
        ws[lane] = z;
    }
    __syncthreads();
    int woff = (wid > 0) ? ws[wid - 1] : 0;
    int base = g_boff[b] + woff + (x - s);
    if (idx < N4) {
        int i = idx * 4;
        int e0 = base, e1 = e0 + v.x, e2 = e1 + v.y, e3 = e2 + v.z;
        g_rowptr[i + 0] = e0; g_cursor[i + 0] = e0;
        g_rowptr[i + 1] = e1; g_cursor[i + 1] = e1;
        g_rowptr[i + 2] = e2; g_cursor[i + 2] = e2;
        g_rowptr[i + 3] = e3; g_cursor[i + 3] = e3;
        g_dis[i + 0] = (v.x > 0) ? rsqrtf((float)v.x) : 0.0f;
        g_dis[i + 1] = (v.y > 0) ? rsqrtf((float)v.y) : 0.0f;
        g_dis[i + 2] = (v.z > 0) ? rsqrtf((float)v.z) : 0.0f;
        g_dis[i + 3] = (v.w > 0) ? rsqrtf((float)v.w) : 0.0f;
    }
}

__global__ void scatter_kernel(const int* __restrict__ h, const int* __restrict__ t, int n) {
    int stride = gridDim.x * blockDim.x;
    for (int i = blockIdx.x * blockDim.x + threadIdx.x; i < n; i += stride) {
        int hh = h[i];
        int pos = atomicAdd(&g_cursor[hh], 1);
        g_ecol[pos] = t[i];
    }
}

// embA = concat(user,item); out = embA/3; S = dis * embA
__global__ void init_kernel(const float* __restrict__ u, const float* __restrict__ it,
                            float* __restrict__ embA, float* __restrict__ out,
                            float* __restrict__ S) {
    int i = blockIdx.x * blockDim.x + threadIdx.x;   // float4 index
    const int total4 = N_NODES * EMB / 4;
    if (i >= total4) return;
    const int ub4 = N_USERS * EMB / 4;
    float4 v = (i < ub4) ? ((const float4*)u)[i] : ((const float4*)it)[i - ub4];
    ((float4*)embA)[i] = v;
    const float third = 1.0f / 3.0f;
    ((float4*)out)[i] = make_float4(v.x * third, v.y * third, v.z * third, v.w * third);
    float d = g_dis[i >> 4];
    ((float4*)S)[i] = make_float4(v.x * d, v.y * d, v.z * d, v.w * d);
}

// ---------------- SPMM: warp per node, pre-scaled gather ----------------
__global__ __launch_bounds__(256) void spmm_kernel(const float* __restrict__ S,
                                                   float* __restrict__ xout) {
    const int lane = threadIdx.x & 31;
    const int n = (blockIdx.x << 3) + (threadIdx.x >> 5);
    if (n >= N_NODES) return;
    const int beg = g_rowptr[n], end = g_rowptr[n + 1];
    unsigned long long acc = 0ull;   // two packed zeros
    int j = beg;
    for (; j + 4 <= end; j += 4) {
        int c0 = g_ecol[j + 0];
        int c1 = g_ecol[j + 1];
        int c2 = g_ecol[j + 2];
        int c3 = g_ecol[j + 3];
        unsigned long long v0 = *((const unsigned long long*)(S + (size_t)c0 * EMB) + lane);
        unsigned long long v1 = *((const unsigned long long*)(S + (size_t)c1 * EMB) + lane);
        unsigned long long v2 = *((const unsigned long long*)(S + (size_t)c2 * EMB) + lane);
        unsigned long long v3 = *((const unsigned long long*)(S + (size_t)c3 * EMB) + lane);
        const unsigned long long one2 = 0x3f8000003f800000ull; // {1.0f,1.0f}
        acc = fma2(v0, one2, acc);
        acc = fma2(v1, one2, acc);
        acc = fma2(v2, one2, acc);
        acc = fma2(v3, one2, acc);
    }
    for (; j < end; j++) {
        int c = g_ecol[j];
        unsigned long long v = *((const unsigned long long*)(S + (size_t)c * EMB) + lane);
        acc = fma2(v, 0x3f8000003f800000ull, acc);
    }
    float dn = g_dis[n];
    float2 a = upk(acc);
    ((float2*)(xout + (size_t)n * EMB))[lane] = make_float2(a.x * dn, a.y * dn);
}

// ---------------- fused intent: y = softmax(X@W)@W^T; xio += y; out += xio/3 ----------------
#define LD1 130          // sXT leading dim (even, padded)
#define LDP 130          // sPT leading dim
#define LDW2 68          // sWT leading dim
#define R1_FLOATS 16640  // max(64*130 + 64*128 = 16512, 128*130 = 16640)
#define SMEMF_BYTES ((R1_FLOATS + 128 * LDW2) * 4)   // 101376 B

__global__ __launch_bounds__(256, 2) void fused_intent_kernel(
    const float* __restrict__ xin, const float* __restrict__ W,
    float* __restrict__ xio, float* __restrict__ out,
    float* __restrict__ Sout) {
    extern __shared__ float smem[];
    float* sXT = smem;                    // [64][LD1]
    float* sW  = smem + 64 * LD1;         // [64][128]
    float* sPT = smem;                    // [128][LDP]  (aliases sXT+sW after sync)
    float* sWT = smem + R1_FLOATS;        // [128][LDW2]

    const int tid = threadIdx.x;
    const int node0 = blockIdx.x * 128;

    // load W row-major (for X@W) and transposed (for P@W^T)
    for (int i = tid; i < 64 * 128 / 4; i += 256)
        *(float4*)(sW + i * 4) = *(const float4*)(W + i * 4);
    for (int i = tid; i < 64 * 128; i += 256) {
        int k = i >> 7, j = i & 127;
        sWT[j * LDW2 + k] = W[i];
    }
    // load X tile transposed (k-major)
    for (int i = tid; i < 128 * 16; i += 256) {
        int m = i >> 4;
        int k4 = (i & 15) << 2;
        int nd = node0 + m;
        float4 v = (nd < N_NODES) ? *(const float4*)(xin + (size_t)nd * EMB + k4)
                                  : make_float4(0.f, 0.f, 0.f, 0.f);
        sXT[(k4 + 0) * LD1 + m] = v.x;
        sXT[(k4 + 1) * LD1 + m] = v.y;
        sXT[(k4 + 2) * LD1 + m] = v.z;
        sXT[(k4 + 3) * LD1 + m] = v.w;
    }
    __syncthreads();

    // ---- phase 1: logits tile, packed rows (8 rows x 8 cols per thread) ----
    const int tj = tid & 15, tm = tid >> 4;
    const int m0 = tm * 8, j0 = tj * 8;
    unsigned long long acc[4][8];
    #pragma unroll
    for (int p = 0; p < 4; p++)
        #pragma unroll
        for (int c = 0; c < 8; c++) acc[p][c] = 0ull;

    #pragma unroll 8
    for (int k = 0; k < 64; k++) {
        unsigned long long a2[4];
        #pragma unroll
        for (int p = 0; p < 4; p++)
            a2[p] = *(const unsigned long long*)(sXT + k * LD1 + m0 + 2 * p);
        float4 b0 = *(const float4*)(sW + k * 128 + j0);
        float4 b1 = *(const float4*)(sW + k * 128 + j0 + 4);
        unsigned long long b2[8];
        b2[0] = pk2(b0.x, b0.x); b2[1] = pk2(b0.y, b0.y);
        b2[2] = pk2(b0.z, b0.z); b2[3] = pk2(b0.w, b0.w);
        b2[4] = pk2(b1.x, b1.x); b2[5] = pk2(b1.y, b1.y);
        b2[6] = pk2(b1.z, b1.z); b2[7] = pk2(b1.w, b1.w);
        #pragma unroll
        for (int p = 0; p < 4; p++)
            #pragma unroll
            for (int c = 0; c < 8; c++)
                acc[p][c] = fma2(a2[p], b2[c], acc[p][c]);
    }
    __syncthreads();   // everyone done reading sXT/sW before sPT overwrite

    // ---- softmax over 128 cols (16 lanes per row group) + store P transposed ----
    #pragma unroll
    for (int p = 0; p < 4; p++) {
        float lo[8], hi[8];
        #pragma unroll
        for (int c = 0; c < 8; c++) {
            float2 t = upk(acc[p][c]);
            lo[c] = t.x; hi[c] = t.y;
        }
        float mx0 = lo[0], mx1 = hi[0];
        #pragma unroll
        for (int c = 1; c < 8; c++) { mx0 = fmaxf(mx0, lo[c]); mx1 = fmaxf(mx1, hi[c]); }
        #pragma unroll
        for (int o = 8; o > 0; o >>= 1) {
            mx0 = fmaxf(mx0, __shfl_xor_sync(0xffffffffu, mx0, o));
            mx1 = fmaxf(mx1, __shfl_xor_sync(0xffffffffu, mx1, o));
        }
        float s0 = 0.f, s1 = 0.f;
        #pragma unroll
        for (int c = 0; c < 8; c++) {
            lo[c] = __expf(lo[c] - mx0); s0 += lo[c];
            hi[c] = __expf(hi[c] - mx1); s1 += hi[c];
        }
        #pragma unroll
        for (int o = 8; o > 0; o >>= 1) {
            s0 += __shfl_xor_sync(0xffffffffu, s0, o);
            s1 += __shfl_xor_sync(0xffffffffu, s1, o);
        }
        float i0 = 1.0f / s0, i1 = 1.0f / s1;
        #pragma unroll
        for (int c = 0; c < 8; c++)
            *(unsigned long long*)(sPT + (size_t)(j0 + c) * LDP + m0 + 2 * p) =
                pk2(lo[c] * i0, hi[c] * i1);
    }
    __syncthreads();

    // ---- phase 2: Y = P @ W^T (8 rows x 4 cols per thread) ----
    const int tn = tid & 15, tm2 = tid >> 4;
    const int mm0 = tm2 * 8, n0 = tn * 4;
    unsigned long long acc2[4][4];
    #pragma unroll
    for (int p = 0; p < 4; p++)
        #pragma unroll
        for (int c = 0; c < 4; c++) acc2[p][c] = 0ull;

    #pragma unroll 8
    for (int j = 0; j < 128; j++) {
        unsigned long long a2[4];
        #pragma unroll
        for (int p = 0; p < 4; p++)
            a2[p] = *(const unsigned long long*)(sPT + (size_t)j * LDP + mm0 + 2 * p);
        float4 b = *(const float4*)(sWT + j * LDW2 + n0);
        unsigned long long b2[4];
        b2[0] = pk2(b.x, b.x); b2[1] = pk2(b.y, b.y);
        b2[2] = pk2(b.z, b.z); b2[3] = pk2(b.w, b.w);
        #pragma unroll
        for (int p = 0; p < 4; p++)
            #pragma unroll
            for (int c = 0; c < 4; c++)
                acc2[p][c] = fma2(a2[p], b2[c], acc2[p][c]);
    }

    // ---- epilogue: y = gnn + intent; xio = y; out += y/3; optional S = dis*y ----
    const float third = 1.0f / 3.0f;
    #pragma unroll
    for (int p = 0; p < 4; p++) {
        float2 t0 = upk(acc2[p][0]);
        float2 t1 = upk(acc2[p][1]);
        float2 t2 = upk(acc2[p][2]);
        float2 t3 = upk(acc2[p][3]);
        #pragma unroll
        for (int h = 0; h < 2; h++) {
            int nd = node0 + mm0 + 2 * p + h;
            if (nd < N_NODES) {
                size_t idx = (size_t)nd * EMB + n0;
                float y0 = h ? t0.y : t0.x, y1 = h ? t1.y : t1.x;
                float y2 = h ? t2.y : t2.x, y3 = h ? t3.y : t3.x;
                float4 g = *(const float4*)(xio + idx);
                float4 y = make_float4(y0 + g.x, y1 + g.y, y2 + g.z, y3 + g.w);
                *(float4*)(xio + idx) = y;
                float4 o = *(const float4*)(out + idx);
                o.x += y.x * third; o.y += y.y * third;
                o.z += y.z * third; o.w += y.w * third;
                *(float4*)(out + idx) = o;
                if (Sout) {
                    float d = g_dis[nd];
                    *(float4*)(Sout + idx) =
                        make_float4(y.x * d, y.y * d, y.z * d, y.w * d);
                }
            }
        }
    }
}

// ---------------- launch ----------------
extern "C" void kernel_launch(void* const* d_in, const int* in_sizes, int n_in,
                              void* d_out, int out_size) {
    const float* user = (const float*)d_in[0];
    const float* item = (const float*)d_in[1];
    const float* W    = (const float*)d_in[2];
    const int*   hix  = (const int*)d_in[3];
    const int*   tix  = (const int*)d_in[4];
    const int n_edges = in_sizes[3];
    float* out = (float*)d_out;

    cudaFuncSetAttribute(fused_intent_kernel,
                         cudaFuncAttributeMaxDynamicSharedMemorySize, SMEMF_BYTES);

    float *A, *B, *S;
    cudaGetSymbolAddress((void**)&A, g_embA);
    cudaGetSymbolAddress((void**)&B, g_embB);
    cudaGetSymbolAddress((void**)&S, g_embS);

    const int TB = 256;
    zero_deg_kernel<<<(N_NODES + TB - 1) / TB, TB>>>();
    hist_kernel<<<4096, TB>>>(hix, n_edges);
    scan_bsum_kernel<<<NBLK, 1024>>>();
    scan_boff_kernel<<<1, 64>>>(n_edges);
    scan_write_kernel<<<NBLK, 1024>>>();
    scatter_kernel<<<4096, TB>>>(hix, tix, n_edges);
    init_kernel<<<(N_NODES * EMB / 4 + TB - 1) / TB, TB>>>(user, item, A, out, S);

    const int spmm_blocks = (N_NODES + 7) / 8;
    const int tile_blocks = (N_NODES + 127) / 128;

    // layer 0
    spmm_kernel<<<spmm_blocks, TB>>>(S, B);
    fused_intent_kernel<<<tile_blocks, TB, SMEMF_BYTES>>>(A, W, B, out, S);
    // layer 1
    spmm_kernel<<<spmm_blocks, TB>>>(S, A);
    fused_intent_kernel<<<tile_blocks, TB, SMEMF_BYTES>>>(B, W, A, out, nullptr);
}

// round 4
// speedup vs baseline: 1.4663x; 1.0206x over previous
#include <cuda_runtime.h>
#include <cuda_fp16.h>
#include <math.h>

#define N_USERS 100000
#define N_ITEMS 50000
#define N_NODES 150000
#define EMB 64
#define NINT 128
#define MAX_EDGES 4000000

#define N4 ((N_NODES + 3) / 4)          // 37500 int4 chunks of deg
#define NBLK ((N4 + 1023) / 1024)       // 37 scan blocks

// ---------------- static device scratch ----------------
__device__ int    g_deg[N_NODES];
__device__ float  g_dis[N_NODES];
__device__ int    g_rowptr[N_NODES + 1];
__device__ int    g_cursor[N_NODES];
__device__ int    g_ecol[MAX_EDGES];
__device__ int    g_bsum[NBLK];
__device__ int    g_boff[NBLK];
__device__ float  g_embA[(size_t)N_NODES * EMB];
__device__ float  g_embB[(size_t)N_NODES * EMB];
__device__ __half g_embS[(size_t)N_NODES * EMB];   // dis-scaled spmm input (fp16)

// ---------------- packed fp32x2 helpers ----------------
__device__ __forceinline__ unsigned long long fma2(unsigned long long a,
                                                   unsigned long long b,
                                                   unsigned long long c) {
    unsigned long long d;
    asm("fma.rn.f32x2 %0, %1, %2, %3;" : "=l"(d) : "l"(a), "l"(b), "l"(c));
    return d;
}
__device__ __forceinline__ unsigned long long pk2(float x, float y) {
    unsigned long long r;
    asm("mov.b64 %0, {%1, %2};" : "=l"(r) : "f"(x), "f"(y));
    return r;
}
__device__ __forceinline__ float2 upk(unsigned long long v) {
    float2 f;
    asm("mov.b64 {%0, %1}, %2;" : "=f"(f.x), "=f"(f.y) : "l"(v));
    return f;
}

// ---------------- precompute ----------------
__global__ void zero_deg_kernel() {
    int i = blockIdx.x * blockDim.x + threadIdx.x;
    if (i < N_NODES) g_deg[i] = 0;
}

__global__ void hist_kernel(const int* __restrict__ h, int n) {
    int stride = gridDim.x * blockDim.x;
    for (int i = blockIdx.x * blockDim.x + threadIdx.x; i < n; i += stride)
        atomicAdd(&g_deg[h[i]], 1);
}

// phase 1: per-block sums of deg (4096 ints / block)
__global__ __launch_bounds__(1024) void scan_bsum_kernel() {
    __shared__ int ws[32];
    int t = threadIdx.x, b = blockIdx.x;
    int idx = b * 1024 + t;
    int4 v = (idx < N4) ? ((const int4*)g_deg)[idx] : make_int4(0, 0, 0, 0);
    int s = v.x + v.y + v.z + v.w;
    #pragma unroll
    for (int o = 16; o; o >>= 1) s += __shfl_xor_sync(0xffffffffu, s, o);
    if ((t & 31) == 0) ws[t >> 5] = s;
    __syncthreads();
    if (t < 32) {
        int x = ws[t];
        #pragma unroll
        for (int o = 16; o; o >>= 1) x += __shfl_xor_sync(0xffffffffu, x, o);
        if (t == 0) g_bsum[b] = x;
    }
}

// phase 2: exclusive scan of NBLK(=37) block sums
__global__ void scan_boff_kernel(int n_edges) {
    __shared__ int tmp[2];
    int t = threadIdx.x;   // 64 threads
    int v = (t < NBLK) ? g_bsum[t] : 0;
    int lane = t & 31, w = t >> 5;
    int x = v;
    #pragma unroll
    for (int o = 1; o < 32; o <<= 1) {
        int y = __shfl_up_sync(0xffffffffu, x, o);
        if (lane >= o) x += y;
    }
    if (lane == 31) tmp[w] = x;
    __syncthreads();
    int add = (w == 1) ? tmp[0] : 0;
    if (t < NBLK) g_boff[t] = x - v + add;
    if (t == 0) g_rowptr[N_NODES] = n_edges;
}

// phase 3: full exclusive scan write (rowptr, cursor) + dis
__global__ __launch_bounds__(1024) void scan_write_kernel() {
    __shared__ int ws[32];
    int t = threadIdx.x, b = blockIdx.x;
    int lane = t & 31, wid = t >> 5;
    int idx = b * 1024 + t;
    int4 v = (idx < N4) ? ((const int4*)g_deg)[idx] : make_int4(0, 0, 0, 0);
    int s = v.x + v.y + v.z + v.w;
    int x = s;
    #pragma unroll
    for (int o = 1; o < 32; o <<= 1) {
        int y = __shfl_up_sync(0xffffffffu, x, o);
        if (lane >= o) x += y;
    }
    if (lane == 31) ws[wid] = x;
    __syncthreads();
    if (wid == 0) {
        int z = ws[lane];
        #pragma unroll
        for (int o = 1; o < 32; o <<= 1) {
            int y = __shfl_up_sync(0xffffffffu, z, o);
            if (lane >= o) z += y;
        }
        ws[lane] = z;
    }
    __syncthreads();
    int woff = (wid > 0) ? ws[wid - 1] : 0;
    int base = g_boff[b] + woff + (x - s);
    if (idx < N4) {
        int i = idx * 4;
        int e0 = base, e1 = e0 + v.x, e2 = e1 + v.y, e3 = e2 + v.z;
        g_rowptr[i + 0] = e0; g_cursor[i + 0] = e0;
        g_rowptr[i + 1] = e1; g_cursor[i + 1] = e1;
        g_rowptr[i + 2] = e2; g_cursor[i + 2] = e2;
        g_rowptr[i + 3] = e3; g_cursor[i + 3] = e3;
        g_dis[i + 0] = (v.x > 0) ? rsqrtf((float)v.x) : 0.0f;
        g_dis[i + 1] = (v.y > 0) ? rsqrtf((float)v.y) : 0.0f;
        g_dis[i + 2] = (v.z > 0) ? rsqrtf((float)v.z) : 0.0f;
        g_dis[i + 3] = (v.w > 0) ? rsqrtf((float)v.w) : 0.0f;
    }
}

__global__ void scatter_kernel(const int* __restrict__ h, const int* __restrict__ t, int n) {
    int stride = gridDim.x * blockDim.x;
    for (int i = blockIdx.x * blockDim.x + threadIdx.x; i < n; i += stride) {
        int hh = h[i];
        int pos = atomicAdd(&g_cursor[hh], 1);
        g_ecol[pos] = t[i];
    }
}

// embA = concat(user,item); out = embA/3; S = half(dis * embA)
__global__ void init_kernel(const float* __restrict__ u, const float* __restrict__ it,
                            float* __restrict__ embA, float* __restrict__ out,
                            __half* __restrict__ S) {
    int i = blockIdx.x * blockDim.x + threadIdx.x;   // float4 index
    const int total4 = N_NODES * EMB / 4;
    if (i >= total4) return;
    const int ub4 = N_USERS * EMB / 4;
    float4 v = (i < ub4) ? ((const float4*)u)[i] : ((const float4*)it)[i - ub4];
    ((float4*)embA)[i] = v;
    const float third = 1.0f / 3.0f;
    ((float4*)out)[i] = make_float4(v.x * third, v.y * third, v.z * third, v.w * third);
    float d = g_dis[i >> 4];
    ((__half2*)S)[i * 2 + 0] = __floats2half2_rn(v.x * d, v.y * d);
    ((__half2*)S)[i * 2 + 1] = __floats2half2_rn(v.z * d, v.w * d);
}

// ---------------- SPMM: warp per node, fp16 gather (pre-scaled) ----------------
__global__ __launch_bounds__(256) void spmm_kernel(const __half* __restrict__ S,
                                                   float* __restrict__ xout) {
    const int lane = threadIdx.x & 31;
    const int n = (blockIdx.x << 3) + (threadIdx.x >> 5);
    if (n >= N_NODES) return;
    const int beg = g_rowptr[n], end = g_rowptr[n + 1];
    const __half2* S2 = (const __half2*)S;
    float ax = 0.f, ay = 0.f;
    int j = beg;
    for (; j + 4 <= end; j += 4) {
        int c0 = g_ecol[j + 0];
        int c1 = g_ecol[j + 1];
        int c2 = g_ecol[j + 2];
        int c3 = g_ecol[j + 3];
        float2 f0 = __half22float2(S2[c0 * 32 + lane]);
        float2 f1 = __half22float2(S2[c1 * 32 + lane]);
        float2 f2 = __half22float2(S2[c2 * 32 + lane]);
        float2 f3 = __half22float2(S2[c3 * 32 + lane]);
        ax += (f0.x + f1.x) + (f2.x + f3.x);
        ay += (f0.y + f1.y) + (f2.y + f3.y);
    }
    for (; j < end; j++) {
        int c = g_ecol[j];
        float2 f = __half22float2(S2[c * 32 + lane]);
        ax += f.x; ay += f.y;
    }
    float dn = g_dis[n];
    ((float2*)(xout + (size_t)n * EMB))[lane] = make_float2(ax * dn, ay * dn);
}

// ---------------- fused intent: y = softmax(X@W)@W^T; xio += y; out += xio/3 ----------------
#define LD1 130          // sXT leading dim (even, padded)
#define LDP 130          // sPT leading dim
#define LDW2 68          // sWT leading dim
#define R1_FLOATS 16640  // max(64*130 + 64*128 = 16512, 128*130 = 16640)
#define SMEMF_BYTES ((R1_FLOATS + 128 * LDW2) * 4)   // 101376 B

__global__ __launch_bounds__(256, 2) void fused_intent_kernel(
    const float* __restrict__ xin, const float* __restrict__ W,
    float* __restrict__ xio, float* __restrict__ out,
    __half* __restrict__ Sout) {
    extern __shared__ float smem[];
    float* sXT = smem;                    // [64][LD1]
    float* sW  = smem + 64 * LD1;         // [64][128]
    float* sPT = smem;                    // [128][LDP]  (aliases sXT+sW after sync)
    float* sWT = smem + R1_FLOATS;        // [128][LDW2]

    const int tid = threadIdx.x;
    const int node0 = blockIdx.x * 128;

    // load W row-major (for X@W) and transposed (for P@W^T)
    for (int i = tid; i < 64 * 128 / 4; i += 256)
        *(float4*)(sW + i * 4) = *(const float4*)(W + i * 4);
    for (int i = tid; i < 64 * 128; i += 256) {
        int k = i >> 7, j = i & 127;
        sWT[j * LDW2 + k] = W[i];
    }
    // load X tile transposed (k-major)
    for (int i = tid; i < 128 * 16; i += 256) {
        int m = i >> 4;
        int k4 = (i & 15) << 2;
        int nd = node0 + m;
        float4 v = (nd < N_NODES) ? *(const float4*)(xin + (size_t)nd * EMB + k4)
                                  : make_float4(0.f, 0.f, 0.f, 0.f);
        sXT[(k4 + 0) * LD1 + m] = v.x;
        sXT[(k4 + 1) * LD1 + m] = v.y;
        sXT[(k4 + 2) * LD1 + m] = v.z;
        sXT[(k4 + 3) * LD1 + m] = v.w;
    }
    __syncthreads();

    // ---- phase 1: logits tile, packed rows (8 rows x 8 cols per thread) ----
    const int tj = tid & 15, tm = tid >> 4;
    const int m0 = tm * 8, j0 = tj * 8;
    unsigned long long acc[4][8];
    #pragma unroll
    for (int p = 0; p < 4; p++)
        #pragma unroll
        for (int c = 0; c < 8; c++) acc[p][c] = 0ull;

    #pragma unroll 8
    for (int k = 0; k < 64; k++) {
        unsigned long long a2[4];
        #pragma unroll
        for (int p = 0; p < 4; p++)
            a2[p] = *(const unsigned long long*)(sXT + k * LD1 + m0 + 2 * p);
        float4 b0 = *(const float4*)(sW + k * 128 + j0);
        float4 b1 = *(const float4*)(sW + k * 128 + j0 + 4);
        unsigned long long b2[8];
        b2[0] = pk2(b0.x, b0.x); b2[1] = pk2(b0.y, b0.y);
        b2[2] = pk2(b0.z, b0.z); b2[3] = pk2(b0.w, b0.w);
        b2[4] = pk2(b1.x, b1.x); b2[5] = pk2(b1.y, b1.y);
        b2[6] = pk2(b1.z, b1.z); b2[7] = pk2(b1.w, b1.w);
        #pragma unroll
        for (int p = 0; p < 4; p++)
            #pragma unroll
            for (int c = 0; c < 8; c++)
                acc[p][c] = fma2(a2[p], b2[c], acc[p][c]);
    }
    __syncthreads();   // everyone done reading sXT/sW before sPT overwrite

    // ---- softmax over 128 cols (16 lanes per row group) + store P transposed ----
    #pragma unroll
    for (int p = 0; p < 4; p++) {
        float lo[8], hi[8];
        #pragma unroll
        for (int c = 0; c < 8; c++) {
            float2 t = upk(acc[p][c]);
            lo[c] = t.x; hi[c] = t.y;
        }
        float mx0 = lo[0], mx1 = hi[0];
        #pragma unroll
        for (int c = 1; c < 8; c++) { mx0 = fmaxf(mx0, lo[c]); mx1 = fmaxf(mx1, hi[c]); }
        #pragma unroll
        for (int o = 8; o > 0; o >>= 1) {
            mx0 = fmaxf(mx0, __shfl_xor_sync(0xffffffffu, mx0, o));
            mx1 = fmaxf(mx1, __shfl_xor_sync(0xffffffffu, mx1, o));
        }
        float s0 = 0.f, s1 = 0.f;
        #pragma unroll
        for (int c = 0; c < 8; c++) {
            lo[c] = __expf(lo[c] - mx0); s0 += lo[c];
            hi[c] = __expf(hi[c] - mx1); s1 += hi[c];
        }
        #pragma unroll
        for (int o = 8; o > 0; o >>= 1) {
            s0 += __shfl_xor_sync(0xffffffffu, s0, o);
            s1 += __shfl_xor_sync(0xffffffffu, s1, o);
        }
        float i0 = 1.0f / s0, i1 = 1.0f / s1;
        #pragma unroll
        for (int c = 0; c < 8; c++)
            *(unsigned long long*)(sPT + (size_t)(j0 + c) * LDP + m0 + 2 * p) =
                pk2(lo[c] * i0, hi[c] * i1);
    }
    __syncthreads();

    // ---- phase 2: Y = P @ W^T (8 rows x 4 cols per thread) ----
    const int tn = tid & 15, tm2 = tid >> 4;
    const int mm0 = tm2 * 8, n0 = tn * 4;
    unsigned long long acc2[4][4];
    #pragma unroll
    for (int p = 0; p < 4; p++)
        #pragma unroll
        for (int c = 0; c < 4; c++) acc2[p][c] = 0ull;

    #pragma unroll 8
    for (int j = 0; j < 128; j++) {
        unsigned long long a2[4];
        #pragma unroll
        for (int p = 0; p < 4; p++)
            a2[p] = *(const unsigned long long*)(sPT + (size_t)j * LDP + mm0 + 2 * p);
        float4 b = *(const float4*)(sWT + j * LDW2 + n0);
        unsigned long long b2[4];
        b2[0] = pk2(b.x, b.x); b2[1] = pk2(b.y, b.y);
        b2[2] = pk2(b.z, b.z); b2[3] = pk2(b.w, b.w);
        #pragma unroll
        for (int p = 0; p < 4; p++)
            #pragma unroll
            for (int c = 0; c < 4; c++)
                acc2[p][c] = fma2(a2[p], b2[c], acc2[p][c]);
    }

    // ---- epilogue: y = gnn + intent; xio = y; out += y/3; optional S = half(dis*y) ----
    const float third = 1.0f / 3.0f;
    #pragma unroll
    for (int p = 0; p < 4; p++) {
        float2 t0 = upk(acc2[p][0]);
        float2 t1 = upk(acc2[p][1]);
        float2 t2 = upk(acc2[p][2]);
        float2 t3 = upk(acc2[p][3]);
        #pragma unroll
        for (int h = 0; h < 2; h++) {
            int nd = node0 + mm0 + 2 * p + h;
            if (nd < N_NODES) {
                size_t idx = (size_t)nd * EMB + n0;
                float y0 = h ? t0.y : t0.x, y1 = h ? t1.y : t1.x;
                float y2 = h ? t2.y : t2.x, y3 = h ? t3.y : t3.x;
                float4 g = *(const float4*)(xio + idx);
                float4 y = make_float4(y0 + g.x, y1 + g.y, y2 + g.z, y3 + g.w);
                *(float4*)(xio + idx) = y;
                float4 o = *(const float4*)(out + idx);
                o.x += y.x * third; o.y += y.y * third;
                o.z += y.z * third; o.w += y.w * third;
                *(float4*)(out + idx) = o;
                if (Sout) {
                    float d = g_dis[nd];
                    ((__half2*)(Sout + idx))[0] = __floats2half2_rn(y.x * d, y.y * d);
                    ((__half2*)(Sout + idx))[1] = __floats2half2_rn(y.z * d, y.w * d);
                }
            }
        }
    }
}

// ---------------- launch ----------------
extern "C" void kernel_launch(void* const* d_in, const int* in_sizes, int n_in,
                              void* d_out, int out_size) {
    const float* user = (const float*)d_in[0];
    const float* item = (const float*)d_in[1];
    const float* W    = (const float*)d_in[2];
    const int*   hix  = (const int*)d_in[3];
    const int*   tix  = (const int*)d_in[4];
    const int n_edges = in_sizes[3];
    float* out = (float*)d_out;

    cudaFuncSetAttribute(fused_intent_kernel,
                         cudaFuncAttributeMaxDynamicSharedMemorySize, SMEMF_BYTES);

    float *A, *B;
    __half* S;
    cudaGetSymbolAddress((void**)&A, g_embA);
    cudaGetSymbolAddress((void**)&B, g_embB);
    cudaGetSymbolAddress((void**)&S, g_embS);

    const int TB = 256;
    zero_deg_kernel<<<(N_NODES + TB - 1) / TB, TB>>>();
    hist_kernel<<<4096, TB>>>(hix, n_edges);
    scan_bsum_kernel<<<NBLK, 1024>>>();
    scan_boff_kernel<<<1, 64>>>(n_edges);
    scan_write_kernel<<<NBLK, 1024>>>();
    scatter_kernel<<<4096, TB>>>(hix, tix, n_edges);
    init_kernel<<<(N_NODES * EMB / 4 + TB - 1) / TB, TB>>>(user, item, A, out, S);

    const int spmm_blocks = (N_NODES + 7) / 8;
    const int tile_blocks = (N_NODES + 127) / 128;

    // layer 0
    spmm_kernel<<<spmm_blocks, TB>>>(S, B);
    fused_intent_kernel<<<tile_blocks, TB, SMEMF_BYTES>>>(A, W, B, out, S);
    // layer 1
    spmm_kernel<<<spmm_blocks, TB>>>(S, A);
    fused_intent_kernel<<<tile_blocks, TB, SMEMF_BYTES>>>(B, W, A, out, nullptr);
}

// round 5
// speedup vs baseline: 1.4857x; 1.0132x over previous
#include <cuda_runtime.h>
#include <cuda_fp16.h>
#include <math.h>

#define N_USERS 100000
#define N_ITEMS 50000
#define N_NODES 150000
#define EMB 64
#define NINT 128
#define MAX_EDGES 4000000

#define N4 ((N_NODES + 3) / 4)          // 37500 int4 chunks of deg
#define NBLK ((N4 + 1023) / 1024)       // 37 scan blocks

// ---------------- static device scratch ----------------
__device__ int    g_deg[N_NODES];
__device__ float  g_dis[N_NODES];
__device__ int    g_rowptr[N_NODES + 1];
__device__ int    g_cursor[N_NODES];
__device__ int    g_ecol[MAX_EDGES];
__device__ volatile unsigned long long g_state[NBLK];   // lookback: (flag<<32)|sum
__device__ float  g_embA[(size_t)N_NODES * EMB];
__device__ float  g_embB[(size_t)N_NODES * EMB];
__device__ __half g_embS[(size_t)N_NODES * EMB];   // dis-scaled spmm input (fp16)

// ---------------- packed fp32x2 helpers ----------------
__device__ __forceinline__ unsigned long long fma2(unsigned long long a,
                                                   unsigned long long b,
                                                   unsigned long long c) {
    unsigned long long d;
    asm("fma.rn.f32x2 %0, %1, %2, %3;" : "=l"(d) : "l"(a), "l"(b), "l"(c));
    return d;
}
__device__ __forceinline__ unsigned long long pk2(float x, float y) {
    unsigned long long r;
    asm("mov.b64 %0, {%1, %2};" : "=l"(r) : "f"(x), "f"(y));
    return r;
}
__device__ __forceinline__ float2 upk(unsigned long long v) {
    float2 f;
    asm("mov.b64 {%0, %1}, %2;" : "=f"(f.x), "=f"(f.y) : "l"(v));
    return f;
}

// ---------------- precompute ----------------
__global__ void hist_kernel(const int* __restrict__ h, int n) {
    int stride = gridDim.x * blockDim.x;
    for (int i = blockIdx.x * blockDim.x + threadIdx.x; i < n; i += stride)
        atomicAdd(&g_deg[h[i]], 1);
}

// single-pass decoupled-lookback scan: deg -> rowptr/cursor (exclusive), dis
__global__ __launch_bounds__(1024) void scan_kernel(int n_edges) {
    __shared__ int ws[32];
    __shared__ int s_excl;
    const int t = threadIdx.x, b = blockIdx.x;
    const int lane = t & 31, wid = t >> 5;
    const int idx = b * 1024 + t;
    int4 v = (idx < N4) ? ((const int4*)g_deg)[idx] : make_int4(0, 0, 0, 0);
    int s = v.x + v.y + v.z + v.w;
    int x = s;
    #pragma unroll
    for (int o = 1; o < 32; o <<= 1) {
        int y = __shfl_up_sync(0xffffffffu, x, o);
        if (lane >= o) x += y;
    }
    if (lane == 31) ws[wid] = x;
    __syncthreads();
    if (wid == 0) {
        int z = ws[lane];
        #pragma unroll
        for (int o = 1; o < 32; o <<= 1) {
            int y = __shfl_up_sync(0xffffffffu, z, o);
            if (lane >= o) z += y;
        }
        ws[lane] = z;
    }
    __syncthreads();
    const int total = ws[31];

    if (t == 0) {
        if (b == 0) {
            g_state[0] = (2ull << 32) | (unsigned)total;
            s_excl = 0;
        } else {
            g_state[b] = (1ull << 32) | (unsigned)total;
            int excl = 0;
            int p = b - 1;
            while (true) {
                unsigned long long st;
                do { st = g_state[p]; } while ((st >> 32) == 0ull);
                excl += (int)(unsigned)st;
                if ((st >> 32) == 2ull) break;
                p--;
            }
            g_state[b] = (2ull << 32) | (unsigned)(excl + total);
            s_excl = excl;
        }
    }
    __syncthreads();

    int base = s_excl + ((wid > 0) ? ws[wid - 1] : 0) + (x - s);
    if (idx < N4) {
        int i = idx * 4;
        int e0 = base, e1 = e0 + v.x, e2 = e1 + v.y, e3 = e2 + v.z;
        g_rowptr[i + 0] = e0; g_cursor[i + 0] = e0;
        g_rowptr[i + 1] = e1; g_cursor[i + 1] = e1;
        g_rowptr[i + 2] = e2; g_cursor[i + 2] = e2;
        g_rowptr[i + 3] = e3; g_cursor[i + 3] = e3;
        g_dis[i + 0] = (v.x > 0) ? rsqrtf((float)v.x) : 0.0f;
        g_dis[i + 1] = (v.y > 0) ? rsqrtf((float)v.y) : 0.0f;
        g_dis[i + 2] = (v.z > 0) ? rsqrtf((float)v.z) : 0.0f;
        g_dis[i + 3] = (v.w > 0) ? rsqrtf((float)v.w) : 0.0f;
    }
    if (b == 0 && t == 0) g_rowptr[N_NODES] = n_edges;
}

// fused: CSR column scatter + embA/out/S initialization
__global__ void scatter_init_kernel(const int* __restrict__ h, const int* __restrict__ t,
                                    int n,
                                    const float* __restrict__ u, const float* __restrict__ it,
                                    float* __restrict__ embA, float* __restrict__ out,
                                    __half* __restrict__ S) {
    const int stride = gridDim.x * blockDim.x;
    const int tid0 = blockIdx.x * blockDim.x + threadIdx.x;
    const int total4 = N_NODES * EMB / 4;
    const int ub4 = N_USERS * EMB / 4;
    const float third = 1.0f / 3.0f;
    for (int i = tid0; i < total4; i += stride) {
        float4 v = (i < ub4) ? ((const float4*)u)[i] : ((const float4*)it)[i - ub4];
        ((float4*)embA)[i] = v;
        ((float4*)out)[i] = make_float4(v.x * third, v.y * third, v.z * third, v.w * third);
        float d = g_dis[i >> 4];
        ((__half2*)S)[i * 2 + 0] = __floats2half2_rn(v.x * d, v.y * d);
        ((__half2*)S)[i * 2 + 1] = __floats2half2_rn(v.z * d, v.w * d);
    }
    for (int i = tid0; i < n; i += stride) {
        int hh = h[i];
        int pos = atomicAdd(&g_cursor[hh], 1);
        g_ecol[pos] = t[i];
    }
}

// ---------------- SPMM: warp per node, fp16 gather, 8-deep MLP ----------------
__global__ __launch_bounds__(256) void spmm_kernel(const __half* __restrict__ S,
                                                   float* __restrict__ xout) {
    const int lane = threadIdx.x & 31;
    const int n = (blockIdx.x << 3) + (threadIdx.x >> 5);
    if (n >= N_NODES) return;
    const int beg = g_rowptr[n], end = g_rowptr[n + 1];
    const __half2* S2 = (const __half2*)S;
    float ax = 0.f, ay = 0.f;
    int j = beg;
    // head to int4 alignment
    for (; j < end && (j & 3); j++) {
        float2 f = __half22float2(S2[g_ecol[j] * 32 + lane]);
        ax += f.x; ay += f.y;
    }
    for (; j + 8 <= end; j += 8) {
        int4 ca = *(const int4*)(g_ecol + j);
        int4 cb = *(const int4*)(g_ecol + j + 4);
        __half2 h0 = S2[ca.x * 32 + lane];
        __half2 h1 = S2[ca.y * 32 + lane];
        __half2 h2 = S2[ca.z * 32 + lane];
        __half2 h3 = S2[ca.w * 32 + lane];
        __half2 h4 = S2[cb.x * 32 + lane];
        __half2 h5 = S2[cb.y * 32 + lane];
        __half2 h6 = S2[cb.z * 32 + lane];
        __half2 h7 = S2[cb.w * 32 + lane];
        float2 f0 = __half22float2(h0), f1 = __half22float2(h1);
        float2 f2 = __half22float2(h2), f3 = __half22float2(h3);
        float2 f4 = __half22float2(h4), f5 = __half22float2(h5);
        float2 f6 = __half22float2(h6), f7 = __half22float2(h7);
        ax += ((f0.x + f1.x) + (f2.x + f3.x)) + ((f4.x + f5.x) + (f6.x + f7.x));
        ay += ((f0.y + f1.y) + (f2.y + f3.y)) + ((f4.y + f5.y) + (f6.y + f7.y));
    }
    for (; j + 4 <= end; j += 4) {
        int4 c = *(const int4*)(g_ecol + j);
        float2 f0 = __half22float2(S2[c.x * 32 + lane]);
        float2 f1 = __half22float2(S2[c.y * 32 + lane]);
        float2 f2 = __half22float2(S2[c.z * 32 + lane]);
        float2 f3 = __half22float2(S2[c.w * 32 + lane]);
        ax += (f0.x + f1.x) + (f2.x + f3.x);
        ay += (f0.y + f1.y) + (f2.y + f3.y);
    }
    for (; j < end; j++) {
        float2 f = __half22float2(S2[g_ecol[j] * 32 + lane]);
        ax += f.x; ay += f.y;
    }
    float dn = g_dis[n];
    ((float2*)(xout + (size_t)n * EMB))[lane] = make_float2(ax * dn, ay * dn);
}

// ---------------- fused intent: y = softmax(X@W)@W^T; xio += y; out += xio/3 ----------------
#define LD1 130          // sXT leading dim (even, padded)
#define LDP 130          // sPT leading dim
#define LDW2 68          // sWT leading dim
#define R1_FLOATS 16640  // max(64*130 + 64*128 = 16512, 128*130 = 16640)
#define SMEMF_BYTES ((R1_FLOATS + 128 * LDW2) * 4)   // 101376 B

__global__ __launch_bounds__(256, 2) void fused_intent_kernel(
    const float* __restrict__ xin, const float* __restrict__ W,
    float* __restrict__ xio, float* __restrict__ out,
    __half* __restrict__ Sout) {
    extern __shared__ float smem[];
    float* sXT = smem;                    // [64][LD1]
    float* sW  = smem + 64 * LD1;         // [64][128]
    float* sPT = smem;                    // [128][LDP]  (aliases sXT+sW after sync)
    float* sWT = smem + R1_FLOATS;        // [128][LDW2]

    const int tid = threadIdx.x;
    const int node0 = blockIdx.x * 128;

    for (int i = tid; i < 64 * 128 / 4; i += 256)
        *(float4*)(sW + i * 4) = *(const float4*)(W + i * 4);
    for (int i = tid; i < 64 * 128; i += 256) {
        int k = i >> 7, j = i & 127;
        sWT[j * LDW2 + k] = W[i];
    }
    for (int i = tid; i < 128 * 16; i += 256) {
        int m = i >> 4;
        int k4 = (i & 15) << 2;
        int nd = node0 + m;
        float4 v = (nd < N_NODES) ? *(const float4*)(xin + (size_t)nd * EMB + k4)
                                  : make_float4(0.f, 0.f, 0.f, 0.f);
        sXT[(k4 + 0) * LD1 + m] = v.x;
        sXT[(k4 + 1) * LD1 + m] = v.y;
        sXT[(k4 + 2) * LD1 + m] = v.z;
        sXT[(k4 + 3) * LD1 + m] = v.w;
    }
    __syncthreads();

    const int tj = tid & 15, tm = tid >> 4;
    const int m0 = tm * 8, j0 = tj * 8;
    unsigned long long acc[4][8];
    #pragma unroll
    for (int p = 0; p < 4; p++)
        #pragma unroll
        for (int c = 0; c < 8; c++) acc[p][c] = 0ull;

    #pragma unroll 8
    for (int k = 0; k < 64; k++) {
        unsigned long long a2[4];
        #pragma unroll
        for (int p = 0; p < 4; p++)
            a2[p] = *(const unsigned long long*)(sXT + k * LD1 + m0 + 2 * p);
        float4 b0 = *(const float4*)(sW + k * 128 + j0);
        float4 b1 = *(const float4*)(sW + k * 128 + j0 + 4);
        unsigned long long b2[8];
        b2[0] = pk2(b0.x, b0.x); b2[1] = pk2(b0.y, b0.y);
        b2[2] = pk2(b0.z, b0.z); b2[3] = pk2(b0.w, b0.w);
        b2[4] = pk2(b1.x, b1.x); b2[5] = pk2(b1.y, b1.y);
        b2[6] = pk2(b1.z, b1.z); b2[7] = pk2(b1.w, b1.w);
        #pragma unroll
        for (int p = 0; p < 4; p++)
            #pragma unroll
            for (int c = 0; c < 8; c++)
                acc[p][c] = fma2(a2[p], b2[c], acc[p][c]);
    }
    __syncthreads();

    #pragma unroll
    for (int p = 0; p < 4; p++) {
        float lo[8], hi[8];
        #pragma unroll
        for (int c = 0; c < 8; c++) {
            float2 t = upk(acc[p][c]);
            lo[c] = t.x; hi[c] = t.y;
        }
        float mx0 = lo[0], mx1 = hi[0];
        #pragma unroll
        for (int c = 1; c < 8; c++) { mx0 = fmaxf(mx0, lo[c]); mx1 = fmaxf(mx1, hi[c]); }
        #pragma unroll
        for (int o = 8; o > 0; o >>= 1) {
            mx0 = fmaxf(mx0, __shfl_xor_sync(0xffffffffu, mx0, o));
            mx1 = fmaxf(mx1, __shfl_xor_sync(0xffffffffu, mx1, o));
        }
        float s0 = 0.f, s1 = 0.f;
        #pragma unroll
        for (int c = 0; c < 8; c++) {
            lo[c] = __expf(lo[c] - mx0); s0 += lo[c];
            hi[c] = __expf(hi[c] - mx1); s1 += hi[c];
        }
        #pragma unroll
        for (int o = 8; o > 0; o >>= 1) {
            s0 += __shfl_xor_sync(0xffffffffu, s0, o);
            s1 += __shfl_xor_sync(0xffffffffu, s1, o);
        }
        float i0 = 1.0f / s0, i1 = 1.0f / s1;
        #pragma unroll
        for (int c = 0; c < 8; c++)
            *(unsigned long long*)(sPT + (size_t)(j0 + c) * LDP + m0 + 2 * p) =
                pk2(lo[c] * i0, hi[c] * i1);
    }
    __syncthreads();

    const int tn = tid & 15, tm2 = tid >> 4;
    const int mm0 = tm2 * 8, n0 = tn * 4;
    unsigned long long acc2[4][4];
    #pragma unroll
    for (int p = 0; p < 4; p++)
        #pragma unroll
        for (int c = 0; c < 4; c++) acc2[p][c] = 0ull;

    #pragma unroll 8
    for (int j = 0; j < 128; j++) {
        unsigned long long a2[4];
        #pragma unroll
        for (int p = 0; p < 4; p++)
            a2[p] = *(const unsigned long long*)(sPT + (size_t)j * LDP + mm0 + 2 * p);
        float4 b = *(const float4*)(sWT + j * LDW2 + n0);
        unsigned long long b2[4];
        b2[0] = pk2(b.x, b.x); b2[1] = pk2(b.y, b.y);
        b2[2] = pk2(b.z, b.z); b2[3] = pk2(b.w, b.w);
        #pragma unroll
        for (int p = 0; p < 4; p++)
            #pragma unroll
            for (int c = 0; c < 4; c++)
                acc2[p][c] = fma2(a2[p], b2[c], acc2[p][c]);
    }

    const float third = 1.0f / 3.0f;
    #pragma unroll
    for (int p = 0; p < 4; p++) {
        float2 t0 = upk(acc2[p][0]);
        float2 t1 = upk(acc2[p][1]);
        float2 t2 = upk(acc2[p][2]);
        float2 t3 = upk(acc2[p][3]);
        #pragma unroll
        for (int h = 0; h < 2; h++) {
            int nd = node0 + mm0 + 2 * p + h;
            if (nd < N_NODES) {
                size_t idx = (size_t)nd * EMB + n0;
                float y0 = h ? t0.y : t0.x, y1 = h ? t1.y : t1.x;
                float y2 = h ? t2.y : t2.x, y3 = h ? t3.y : t3.x;
                float4 g = *(const float4*)(xio + idx);
                float4 y = make_float4(y0 + g.x, y1 + g.y, y2 + g.z, y3 + g.w);
                *(float4*)(xio + idx) = y;
                float4 o = *(const float4*)(out + idx);
                o.x += y.x * third; o.y += y.y * third;
                o.z += y.z * third; o.w += y.w * third;
                *(float4*)(out + idx) = o;
                if (Sout) {
                    float d = g_dis[nd];
                    ((__half2*)(Sout + idx))[0] = __floats2half2_rn(y.x * d, y.y * d);
                    ((__half2*)(Sout + idx))[1] = __floats2half2_rn(y.z * d, y.w * d);
                }
            }
        }
    }
}

// ---------------- launch ----------------
extern "C" void kernel_launch(void* const* d_in, const int* in_sizes, int n_in,
                              void* d_out, int out_size) {
    const float* user = (const float*)d_in[0];
    const float* item = (const float*)d_in[1];
    const float* W    = (const float*)d_in[2];
    const int*   hix  = (const int*)d_in[3];
    const int*   tix  = (const int*)d_in[4];
    const int n_edges = in_sizes[3];
    float* out = (float*)d_out;

    cudaFuncSetAttribute(fused_intent_kernel,
                         cudaFuncAttributeMaxDynamicSharedMemorySize, SMEMF_BYTES);

    float *A, *B;
    __half* S;
    void *degp, *statep;
    cudaGetSymbolAddress((void**)&A, g_embA);
    cudaGetSymbolAddress((void**)&B, g_embB);
    cudaGetSymbolAddress((void**)&S, g_embS);
    cudaGetSymbolAddress(&degp, g_deg);
    cudaGetSymbolAddress(&statep, g_state);

    const int TB = 256;
    // zero degree counters + lookback state via memset nodes (not kernel launches)
    cudaMemsetAsync(degp, 0, N_NODES * sizeof(int));
    cudaMemsetAsync(statep, 0, NBLK * sizeof(unsigned long long));

    hist_kernel<<<4096, TB>>>(hix, n_edges);                               // launch 1
    scan_kernel<<<NBLK, 1024>>>(n_edges);                                  // launch 2
    scatter_init_kernel<<<4096, TB>>>(hix, tix, n_edges, user, item, A, out, S); // launch 3

    const int spmm_blocks = (N_NODES + 7) / 8;
    const int tile_blocks = (N_NODES + 127) / 128;

    // layer 0
    spmm_kernel<<<spmm_blocks, TB>>>(S, B);                                // launch 4 (profiled)
    fused_intent_kernel<<<tile_blocks, TB, SMEMF_BYTES>>>(A, W, B, out, S);
    // layer 1
    spmm_kernel<<<spmm_blocks, TB>>>(S, A);
    fused_intent_kernel<<<tile_blocks, TB, SMEMF_BYTES>>>(B, W, A, out, nullptr);
}